// round 12
// baseline (speedup 1.0000x reference)
#include <cuda_runtime.h>
#include <cuda_bf16.h>
#include <cstdint>

#define NN 100000
#define NE 600000
#define FF 128

// ---------------- scratch (device globals; no allocation) ----------------
__device__ int   g_deg[NN];
__device__ int   g_off[NN];
__device__ int   g_cur[NN];
__device__ int   g_part[512];
__device__ int   g_csr[NE];
__device__ int   g_is64;
__device__ float g_h1[(long long)NN * FF];
__device__ unsigned short g_wh[5][128 * 128];   // pre-split weights: hi
__device__ unsigned short g_wl[5][128 * 128];   // pre-split weights: lo

// ---------------- init + edge dtype detection ----------------
__global__ void k_init() {
    int i = blockIdx.x * blockDim.x + threadIdx.x;
    if (i < NN) g_deg[i] = 0;
    if (i == 0) g_is64 = 1;
}

__global__ void k_detect(const int* __restrict__ xe) {
    int i = blockIdx.x * blockDim.x + threadIdx.x;
    if (i < NE) {
        if (xe[2 * i + 1] != 0) g_is64 = 0;
    }
}

__device__ __forceinline__ int eidx(const void* xe, int is64, long long i) {
    if (is64) return (int)((const long long*)xe)[i];
    return ((const int*)xe)[i];
}

// ---------------- CSR build ----------------
__global__ void k_deg(const void* __restrict__ xe) {
    int e = blockIdx.x * blockDim.x + threadIdx.x;
    if (e >= NE) return;
    int is64 = g_is64;
    int d = eidx(xe, is64, (long long)NE + e);
    atomicAdd(&g_deg[d], 1);
}

__global__ void k_scan1() {
    __shared__ int sh[512];
    int tid = threadIdx.x;
    int i = blockIdx.x * 512 + tid;
    int v = (i < NN) ? g_deg[i] : 0;
    sh[tid] = v;
    __syncthreads();
    for (int off = 1; off < 512; off <<= 1) {
        int t = 0;
        if (tid >= off) t = sh[tid - off];
        __syncthreads();
        sh[tid] += t;
        __syncthreads();
    }
    if (i < NN) g_off[i] = sh[tid] - v;
    if (tid == 511) g_part[blockIdx.x] = sh[511];
}

__global__ void k_scan2(int nb) {
    __shared__ int sh[512];
    int tid = threadIdx.x;
    int v = (tid < nb) ? g_part[tid] : 0;
    sh[tid] = v;
    __syncthreads();
    for (int off = 1; off < 512; off <<= 1) {
        int t = 0;
        if (tid >= off) t = sh[tid - off];
        __syncthreads();
        sh[tid] += t;
        __syncthreads();
    }
    if (tid < nb) g_part[tid] = sh[tid] - v;
}

__global__ void k_scan3() {
    int i = blockIdx.x * blockDim.x + threadIdx.x;
    if (i < NN) {
        int o = g_off[i] + g_part[i >> 9];
        g_off[i] = o;
        g_cur[i] = o;
    }
}

__global__ void k_fill(const void* __restrict__ xe) {
    int e = blockIdx.x * blockDim.x + threadIdx.x;
    if (e >= NE) return;
    int is64 = g_is64;
    int s = eidx(xe, is64, e);
    int d = eidx(xe, is64, (long long)NE + e);
    int p = atomicAdd(&g_cur[d], 1);
    g_csr[p] = s;
}

// ================= bf16 split GEMM via mma.sync, fused neighbor-mean gather =================
#define PADK 24
#define CH (128 * PADK)                 // ushorts per chunk-tile
// dynamic smem layout (ushort units):
//   Ah[2][CH]@0  Al@6144  Wh@12288  Wl@18432  Hh[8][CH]@24576  Hl@49152
#define SMEM_B (73728 * 2)              // 144 KB

__device__ __forceinline__ uint32_t smem_u32(const void* p) {
    uint32_t a;
    asm("{ .reg .u64 t; cvta.to.shared.u64 t, %1; cvt.u32.u64 %0, t; }" : "=r"(a) : "l"(p));
    return a;
}

#define LDSM_X4(r, a) asm volatile( \
    "ldmatrix.sync.aligned.m8n8.x4.shared.b16 {%0,%1,%2,%3}, [%4];" \
    : "=r"((r)[0]), "=r"((r)[1]), "=r"((r)[2]), "=r"((r)[3]) : "r"(a))
#define LDSM_X2(r, a) asm volatile( \
    "ldmatrix.sync.aligned.m8n8.x2.shared.b16 {%0,%1}, [%2];" \
    : "=r"((r)[0]), "=r"((r)[1]) : "r"(a))
#define MMA16816(c, A, B) asm volatile( \
    "mma.sync.aligned.m16n8k16.row.col.f32.bf16.bf16.f32 " \
    "{%0,%1,%2,%3}, {%4,%5,%6,%7}, {%8,%9}, {%0,%1,%2,%3};" \
    : "+f"((c)[0]), "+f"((c)[1]), "+f"((c)[2]), "+f"((c)[3]) \
    : "r"((A)[0]), "r"((A)[1]), "r"((A)[2]), "r"((A)[3]), "r"((B)[0]), "r"((B)[1]))

__device__ __forceinline__ void split2(float f0, float f1, uint32_t& hw, uint32_t& lw) {
    asm("cvt.rn.bf16x2.f32 %0, %1, %2;" : "=r"(hw) : "f"(f1), "f"(f0));
    float h0 = __uint_as_float(hw << 16);
    float h1 = __uint_as_float(hw & 0xffff0000u);
    float r0 = f0 - h0, r1 = f1 - h1;
    asm("cvt.rn.bf16x2.f32 %0, %1, %2;" : "=r"(lw) : "f"(r1), "f"(r0));
}

// pre-split all 5 weight matrices (f32 -> bf16 hi/lo), 8 elems/thread
__global__ void k_wsplit(const float* w0, const float* w1, const float* w2,
                         const float* w3, const float* w4) {
    int i = (blockIdx.x * blockDim.x + threadIdx.x) * 8;
    if (i >= 5 * 16384) return;
    int idx = i >> 14, off = i & 16383;
    const float* w = idx == 0 ? w0 : idx == 1 ? w1 : idx == 2 ? w2 : idx == 3 ? w3 : w4;
    uint32_t hw[4], lw[4];
#pragma unroll
    for (int q = 0; q < 4; q++) split2(w[off + 2 * q], w[off + 2 * q + 1], hw[q], lw[q]);
    *(uint4*)&g_wh[idx][off] = make_uint4(hw[0], hw[1], hw[2], hw[3]);
    *(uint4*)&g_wl[idx][off] = make_uint4(lw[0], lw[1], lw[2], lw[3]);
}

__device__ __forceinline__ void ld_stage_a(const float* __restrict__ S, int row0,
                                           int kb, int tid, float v[8]) {
    int r = tid >> 1, h = tid & 1;
    int grow = row0 + r;
    if (grow < NN) {
        const float4* p = (const float4*)&S[(long long)grow * FF + kb * 16 + h * 8];
        float4 a = p[0], b = p[1];
        v[0] = a.x; v[1] = a.y; v[2] = a.z; v[3] = a.w;
        v[4] = b.x; v[5] = b.y; v[6] = b.z; v[7] = b.w;
    } else {
#pragma unroll
        for (int q = 0; q < 8; q++) v[q] = 0.f;
    }
}

__device__ __forceinline__ void st_stage_a(unsigned short* H, unsigned short* L,
                                           int tid, const float v[8]) {
    int r = tid >> 1, h = tid & 1;
    uint32_t hw[4], lw[4];
#pragma unroll
    for (int q = 0; q < 4; q++) split2(v[2 * q], v[2 * q + 1], hw[q], lw[q]);
    *(uint4*)&H[r * PADK + h * 8] = make_uint4(hw[0], hw[1], hw[2], hw[3]);
    *(uint4*)&L[r * PADK + h * 8] = make_uint4(lw[0], lw[1], lw[2], lw[3]);
}

__device__ __forceinline__ void ld_stage_w(int widx, int kb, int tid, uint4& hw, uint4& lw) {
    int r = tid >> 1, h = tid & 1;
    hw = *(const uint4*)&g_wh[widx][r * 128 + kb * 16 + h * 8];
    lw = *(const uint4*)&g_wl[widx][r * 128 + kb * 16 + h * 8];
}

__device__ __forceinline__ void st_stage_w(unsigned short* H, unsigned short* L,
                                           int tid, uint4 hw, uint4 lw) {
    int r = tid >> 1, h = tid & 1;
    *(uint4*)&H[r * PADK + h * 8] = hw;
    *(uint4*)&L[r * PADK + h * 8] = lw;
}

// out1 = mean_agg(Xs)@W[wi1]^T + Xs@W[wi2]^T + bias (relu optional)
// if dec: out2 = out1@W[4]^T + bdec
__global__ void __launch_bounds__(256, 1) k_mma(
    const float* __restrict__ Xs,
    int wi1, int wi2,
    const float* __restrict__ bias, float* __restrict__ out1, int relu,
    int dec, const float* __restrict__ bdec, float* __restrict__ out2)
{
    extern __shared__ unsigned short smu[];
    unsigned short* AhS = smu;
    unsigned short* AlS = smu + 2 * CH;
    unsigned short* WhS = smu + 4 * CH;
    unsigned short* WlS = smu + 6 * CH;
    unsigned short* HhS = smu + 8 * CH;    // [8][CH]: agg operand, then h for decoder
    unsigned short* HlS = smu + 16 * CH;

    int tid = threadIdx.x, lane = tid & 31, wid = tid >> 5;
    int row0 = blockIdx.x * 128;
    int m_base = (wid & 1) * 64;
    int n_base = (wid >> 1) * 32;

    // ---- upfront: gather neighbor mean for this CTA's rows into Hhold ----
    {
        int r = tid >> 1, h = tid & 1;
        int grow = row0 + r;
        float areg[64];
#pragma unroll
        for (int q = 0; q < 64; q++) areg[q] = 0.f;
        if (grow < NN) {
            int beg = g_off[grow], dv = g_deg[grow];
            for (int i = 0; i < dv; i++) {
                int s = g_csr[beg + i];
                const float4* bp = (const float4*)&Xs[(long long)s * FF + h * 8];
#pragma unroll
                for (int kb = 0; kb < 8; kb++) {
                    float4 a = bp[kb * 4];
                    float4 b = bp[kb * 4 + 1];
                    areg[kb * 8 + 0] += a.x; areg[kb * 8 + 1] += a.y;
                    areg[kb * 8 + 2] += a.z; areg[kb * 8 + 3] += a.w;
                    areg[kb * 8 + 4] += b.x; areg[kb * 8 + 5] += b.y;
                    areg[kb * 8 + 6] += b.z; areg[kb * 8 + 7] += b.w;
                }
            }
            float inv = 1.0f / (float)(dv > 0 ? dv : 1);
#pragma unroll
            for (int q = 0; q < 64; q++) areg[q] *= inv;
        }
#pragma unroll
        for (int kb = 0; kb < 8; kb++) {
            uint32_t hw[4], lw[4];
#pragma unroll
            for (int q = 0; q < 4; q++)
                split2(areg[kb * 8 + 2 * q], areg[kb * 8 + 2 * q + 1], hw[q], lw[q]);
            *(uint4*)&HhS[kb * CH + r * PADK + h * 8] = make_uint4(hw[0], hw[1], hw[2], hw[3]);
            *(uint4*)&HlS[kb * CH + r * PADK + h * 8] = make_uint4(lw[0], lw[1], lw[2], lw[3]);
        }
    }
    // chunk-0 barrier below orders Hhold fill before first reads

    float acc[4][4][4];
#pragma unroll
    for (int mi = 0; mi < 4; mi++)
#pragma unroll
        for (int ni = 0; ni < 4; ni++)
#pragma unroll
            for (int q = 0; q < 4; q++) acc[mi][ni][q] = 0.f;

    int a_r = (lane & 7) + ((lane >> 3) & 1) * 8;
    int a_c = (lane >> 4) * 8;
    int b_r = lane & 7;
    int b_c = ((lane >> 3) & 1) * 8;

    float av[8];
    uint4 whv, wlv;
    ld_stage_w(wi1, 0, tid, whv, wlv);

    // chunks 0-7: A = agg (from Hhold, read-only); chunks 8-15: A = Xs (ping-pong staged)
    for (int c = 0; c < 16; c++) {
        int buf = c & 1;
        if (c >= 8) st_stage_a(AhS + buf * CH, AlS + buf * CH, tid, av);
        st_stage_w(WhS + buf * CH, WlS + buf * CH, tid, whv, wlv);
        __syncthreads();
        if (c + 1 < 16) {
            if (c + 1 >= 8) ld_stage_a(Xs, row0, (c + 1) & 7, tid, av);
            ld_stage_w((c + 1 >= 8) ? wi2 : wi1, (c + 1) & 7, tid, whv, wlv);
        }
        const unsigned short* Asrc_h = (c < 8) ? (HhS + c * CH) : (AhS + buf * CH);
        const unsigned short* Asrc_l = (c < 8) ? (HlS + c * CH) : (AlS + buf * CH);
        uint32_t Ah4[4][4], Al4[4][4], Bh2[4][2], Bl2[4][2];
#pragma unroll
        for (int mi = 0; mi < 4; mi++) {
            LDSM_X4(Ah4[mi], smem_u32(&Asrc_h[(m_base + mi * 16 + a_r) * PADK + a_c]));
            LDSM_X4(Al4[mi], smem_u32(&Asrc_l[(m_base + mi * 16 + a_r) * PADK + a_c]));
        }
#pragma unroll
        for (int ni = 0; ni < 4; ni++) {
            LDSM_X2(Bh2[ni], smem_u32(&WhS[buf * CH + (n_base + ni * 8 + b_r) * PADK + b_c]));
            LDSM_X2(Bl2[ni], smem_u32(&WlS[buf * CH + (n_base + ni * 8 + b_r) * PADK + b_c]));
        }
#pragma unroll
        for (int mi = 0; mi < 4; mi++)
#pragma unroll
            for (int ni = 0; ni < 4; ni++) {
                MMA16816(acc[mi][ni], Ah4[mi], Bh2[ni]);
                MMA16816(acc[mi][ni], Ah4[mi], Bl2[ni]);
                MMA16816(acc[mi][ni], Al4[mi], Bh2[ni]);
            }
    }

    // epilogue: out1 = acc + bias (relu); if dec, split h back into Hhold
    // (safe: all Hhold reads ended at chunk 7, ordered before the chunk-8 barrier)
#pragma unroll
    for (int ni = 0; ni < 4; ni++) {
        int col = n_base + ni * 8 + (lane & 3) * 2;
        float b0 = bias[col], b1 = bias[col + 1];
        int chunk = col >> 4, kw = col & 15;
#pragma unroll
        for (int mi = 0; mi < 4; mi++) {
            int rr0 = m_base + mi * 16 + (lane >> 2);
            int rr1 = rr0 + 8;
            int r0 = row0 + rr0, r1 = row0 + rr1;
            float2 p0 = make_float2(acc[mi][ni][0] + b0, acc[mi][ni][1] + b1);
            float2 p1 = make_float2(acc[mi][ni][2] + b0, acc[mi][ni][3] + b1);
            if (relu) {
                p0.x = fmaxf(p0.x, 0.f); p0.y = fmaxf(p0.y, 0.f);
                p1.x = fmaxf(p1.x, 0.f); p1.y = fmaxf(p1.y, 0.f);
            }
            if (r0 < NN) *(float2*)&out1[(long long)r0 * FF + col] = p0;
            if (r1 < NN) *(float2*)&out1[(long long)r1 * FF + col] = p1;
            if (dec) {
                uint32_t hw, lw;
                split2(p0.x, p0.y, hw, lw);
                *(uint32_t*)&HhS[chunk * CH + rr0 * PADK + kw] = hw;
                *(uint32_t*)&HlS[chunk * CH + rr0 * PADK + kw] = lw;
                split2(p1.x, p1.y, hw, lw);
                *(uint32_t*)&HhS[chunk * CH + rr1 * PADK + kw] = hw;
                *(uint32_t*)&HlS[chunk * CH + rr1 * PADK + kw] = lw;
            }
        }
    }

    if (!dec) return;

    // decoder: dx = h @ W[4]^T + bdec; A from Hhold, W ping-pong
#pragma unroll
    for (int mi = 0; mi < 4; mi++)
#pragma unroll
        for (int ni = 0; ni < 4; ni++)
#pragma unroll
            for (int q = 0; q < 4; q++) acc[mi][ni][q] = 0.f;

    ld_stage_w(4, 0, tid, whv, wlv);
    for (int c = 0; c < 8; c++) {
        int buf = c & 1;
        st_stage_w(WhS + buf * CH, WlS + buf * CH, tid, whv, wlv);
        __syncthreads();   // @c==0 also orders all epilogue Hhold writes before reads
        if (c + 1 < 8) ld_stage_w(4, c + 1, tid, whv, wlv);
        uint32_t Ah4[4][4], Al4[4][4], Bh2[4][2], Bl2[4][2];
#pragma unroll
        for (int mi = 0; mi < 4; mi++) {
            LDSM_X4(Ah4[mi], smem_u32(&HhS[c * CH + (m_base + mi * 16 + a_r) * PADK + a_c]));
            LDSM_X4(Al4[mi], smem_u32(&HlS[c * CH + (m_base + mi * 16 + a_r) * PADK + a_c]));
        }
#pragma unroll
        for (int ni = 0; ni < 4; ni++) {
            LDSM_X2(Bh2[ni], smem_u32(&WhS[buf * CH + (n_base + ni * 8 + b_r) * PADK + b_c]));
            LDSM_X2(Bl2[ni], smem_u32(&WlS[buf * CH + (n_base + ni * 8 + b_r) * PADK + b_c]));
        }
#pragma unroll
        for (int mi = 0; mi < 4; mi++)
#pragma unroll
            for (int ni = 0; ni < 4; ni++) {
                MMA16816(acc[mi][ni], Ah4[mi], Bh2[ni]);
                MMA16816(acc[mi][ni], Ah4[mi], Bl2[ni]);
                MMA16816(acc[mi][ni], Al4[mi], Bh2[ni]);
            }
    }

#pragma unroll
    for (int ni = 0; ni < 4; ni++) {
        int col = n_base + ni * 8 + (lane & 3) * 2;
        float b0 = bdec[col], b1 = bdec[col + 1];
#pragma unroll
        for (int mi = 0; mi < 4; mi++) {
            int r0 = row0 + m_base + mi * 16 + (lane >> 2);
            int r1 = r0 + 8;
            float2 p0 = make_float2(acc[mi][ni][0] + b0, acc[mi][ni][1] + b1);
            float2 p1 = make_float2(acc[mi][ni][2] + b0, acc[mi][ni][3] + b1);
            if (r0 < NN) *(float2*)&out2[(long long)r0 * FF + col] = p0;
            if (r1 < NN) *(float2*)&out2[(long long)r1 * FF + col] = p1;
        }
    }
}

// ---------------- launch ----------------
extern "C" void kernel_launch(void* const* d_in, const int* in_sizes, int n_in,
                              void* d_out, int out_size)
{
    const float* x    = (const float*)d_in[0];
    const void*  xe   = d_in[1];
    const float* w1l  = (const float*)d_in[2];
    const float* b1l  = (const float*)d_in[3];
    const float* w1r  = (const float*)d_in[4];
    const float* w2l  = (const float*)d_in[5];
    const float* b2l  = (const float*)d_in[6];
    const float* w2r  = (const float*)d_in[7];
    const float* wdec = (const float*)d_in[8];
    const float* bdec = (const float*)d_in[9];

    float* out_h  = (float*)d_out;
    float* out_dx = out_h + (long long)NN * FF;

    float* h1_p = nullptr;
    cudaGetSymbolAddress((void**)&h1_p, g_h1);

    cudaFuncSetAttribute(k_mma, cudaFuncAttributeMaxDynamicSharedMemorySize, SMEM_B);

    int nbScan = (NN + 511) / 512;
    int gE = (NE + 255) / 256;
    int gTc = (NN + 127) / 128;             // 782

    k_init  <<<(NN + 255) / 256, 256>>>();
    k_wsplit<<<40, 256>>>(w1l, w1r, w2l, w2r, wdec);
    k_detect<<<gE, 256>>>((const int*)xe);
    k_deg   <<<gE, 256>>>(xe);
    k_scan1 <<<nbScan, 512>>>();
    k_scan2 <<<1, 512>>>(nbScan);
    k_scan3 <<<(NN + 511) / 512, 512>>>();
    k_fill  <<<gE, 256>>>(xe);

    // conv1 (fused agg + GEMM)
    k_mma<<<gTc, 256, SMEM_B>>>(x, 0, 1, b1l, h1_p, 1, 0, nullptr, nullptr);
    // conv2 + decoder (fused agg + GEMM + decoder)
    k_mma<<<gTc, 256, SMEM_B>>>(h1_p, 2, 3, b2l, out_h, 0, 1, bdec, out_dx);
}

// round 14
// speedup vs baseline: 1.0661x; 1.0661x over previous
#include <cuda_runtime.h>
#include <cuda_bf16.h>
#include <cstdint>

#define NN 100000
#define NE 600000
#define FF 128

// ---------------- scratch (device globals; no allocation) ----------------
__device__ int   g_deg[NN];
__device__ int   g_off[NN];
__device__ int   g_cur[NN];
__device__ int   g_part[512];
__device__ int   g_csr[NE];
__device__ int   g_is64;
__device__ float g_h1[(long long)NN * FF];
__device__ unsigned short g_aggh[(long long)NN * FF];   // pre-split agg: hi
__device__ unsigned short g_aggl[(long long)NN * FF];   // pre-split agg: lo
__device__ unsigned short g_wh[5][128 * 128];           // pre-split weights: hi
__device__ unsigned short g_wl[5][128 * 128];           // pre-split weights: lo

// ---------------- init + edge dtype detection ----------------
__global__ void k_init() {
    int i = blockIdx.x * blockDim.x + threadIdx.x;
    if (i < NN) g_deg[i] = 0;
    if (i == 0) g_is64 = 1;
}

__global__ void k_detect(const int* __restrict__ xe) {
    int i = blockIdx.x * blockDim.x + threadIdx.x;
    if (i < NE) {
        if (xe[2 * i + 1] != 0) g_is64 = 0;
    }
}

__device__ __forceinline__ int eidx(const void* xe, int is64, long long i) {
    if (is64) return (int)((const long long*)xe)[i];
    return ((const int*)xe)[i];
}

// ---------------- CSR build ----------------
__global__ void k_deg(const void* __restrict__ xe) {
    int e = blockIdx.x * blockDim.x + threadIdx.x;
    if (e >= NE) return;
    int is64 = g_is64;
    int d = eidx(xe, is64, (long long)NE + e);
    atomicAdd(&g_deg[d], 1);
}

__global__ void k_scan1() {
    __shared__ int sh[512];
    int tid = threadIdx.x;
    int i = blockIdx.x * 512 + tid;
    int v = (i < NN) ? g_deg[i] : 0;
    sh[tid] = v;
    __syncthreads();
    for (int off = 1; off < 512; off <<= 1) {
        int t = 0;
        if (tid >= off) t = sh[tid - off];
        __syncthreads();
        sh[tid] += t;
        __syncthreads();
    }
    if (i < NN) g_off[i] = sh[tid] - v;
    if (tid == 511) g_part[blockIdx.x] = sh[511];
}

__global__ void k_scan2(int nb) {
    __shared__ int sh[512];
    int tid = threadIdx.x;
    int v = (tid < nb) ? g_part[tid] : 0;
    sh[tid] = v;
    __syncthreads();
    for (int off = 1; off < 512; off <<= 1) {
        int t = 0;
        if (tid >= off) t = sh[tid - off];
        __syncthreads();
        sh[tid] += t;
        __syncthreads();
    }
    if (tid < nb) g_part[tid] = sh[tid] - v;
}

__global__ void k_scan3() {
    int i = blockIdx.x * blockDim.x + threadIdx.x;
    if (i < NN) {
        int o = g_off[i] + g_part[i >> 9];
        g_off[i] = o;
        g_cur[i] = o;
    }
}

__global__ void k_fill(const void* __restrict__ xe) {
    int e = blockIdx.x * blockDim.x + threadIdx.x;
    if (e >= NE) return;
    int is64 = g_is64;
    int s = eidx(xe, is64, e);
    int d = eidx(xe, is64, (long long)NE + e);
    int p = atomicAdd(&g_cur[d], 1);
    g_csr[p] = s;
}

__device__ __forceinline__ void split2(float f0, float f1, uint32_t& hw, uint32_t& lw) {
    asm("cvt.rn.bf16x2.f32 %0, %1, %2;" : "=r"(hw) : "f"(f1), "f"(f0));
    float h0 = __uint_as_float(hw << 16);
    float h1 = __uint_as_float(hw & 0xffff0000u);
    float r0 = f0 - h0, r1 = f1 - h1;
    asm("cvt.rn.bf16x2.f32 %0, %1, %2;" : "=r"(lw) : "f"(r1), "f"(r0));
}

// ---------------- mean aggregation: one warp per node, float4 lanes, MLP=4 ----------------
// emits bf16 hi/lo split directly (consumed by k_mma chunks 0-7 as pass-through)
__global__ void k_agg(const float* __restrict__ X) {
    int wid  = (blockIdx.x * blockDim.x + threadIdx.x) >> 5;
    int lane = threadIdx.x & 31;
    if (wid >= NN) return;
    int beg = g_off[wid];
    int d   = g_deg[wid];
    float4 s = make_float4(0.f, 0.f, 0.f, 0.f);
    int i = 0;
    for (; i + 4 <= d; i += 4) {
        int s0 = g_csr[beg + i];
        int s1 = g_csr[beg + i + 1];
        int s2 = g_csr[beg + i + 2];
        int s3 = g_csr[beg + i + 3];
        float4 v0 = *(const float4*)&X[(long long)s0 * FF + lane * 4];
        float4 v1 = *(const float4*)&X[(long long)s1 * FF + lane * 4];
        float4 v2 = *(const float4*)&X[(long long)s2 * FF + lane * 4];
        float4 v3 = *(const float4*)&X[(long long)s3 * FF + lane * 4];
        s.x += (v0.x + v1.x) + (v2.x + v3.x);
        s.y += (v0.y + v1.y) + (v2.y + v3.y);
        s.z += (v0.z + v1.z) + (v2.z + v3.z);
        s.w += (v0.w + v1.w) + (v2.w + v3.w);
    }
    for (; i < d; i++) {
        int s0 = g_csr[beg + i];
        float4 v0 = *(const float4*)&X[(long long)s0 * FF + lane * 4];
        s.x += v0.x; s.y += v0.y; s.z += v0.z; s.w += v0.w;
    }
    float inv = 1.0f / (float)(d > 0 ? d : 1);
    uint32_t h0, l0, h1, l1;
    split2(s.x * inv, s.y * inv, h0, l0);
    split2(s.z * inv, s.w * inv, h1, l1);
    long long base = (long long)wid * FF + lane * 4;
    *(uint2*)&g_aggh[base] = make_uint2(h0, h1);
    *(uint2*)&g_aggl[base] = make_uint2(l0, l1);
}

// ================= bf16 split GEMM via mma.sync =================
#define PADK 24
#define CH (128 * PADK)                 // ushorts per chunk-tile
// dynamic smem layout (ushort units):
//   Ah[2][CH]@0  Al@6144  Wh@12288  Wl@18432  Hh[8][CH]@24576  Hl@49152
#define SMEM_STAGE_B (24576 * 2)        // conv-only: 48 KB
#define SMEM_DEC_B   (73728 * 2)        // conv2+decoder: 144 KB

__device__ __forceinline__ uint32_t smem_u32(const void* p) {
    uint32_t a;
    asm("{ .reg .u64 t; cvta.to.shared.u64 t, %1; cvt.u32.u64 %0, t; }" : "=r"(a) : "l"(p));
    return a;
}

#define LDSM_X4(r, a) asm volatile( \
    "ldmatrix.sync.aligned.m8n8.x4.shared.b16 {%0,%1,%2,%3}, [%4];" \
    : "=r"((r)[0]), "=r"((r)[1]), "=r"((r)[2]), "=r"((r)[3]) : "r"(a))
#define LDSM_X2(r, a) asm volatile( \
    "ldmatrix.sync.aligned.m8n8.x2.shared.b16 {%0,%1}, [%2];" \
    : "=r"((r)[0]), "=r"((r)[1]) : "r"(a))
#define MMA16816(c, A, B) asm volatile( \
    "mma.sync.aligned.m16n8k16.row.col.f32.bf16.bf16.f32 " \
    "{%0,%1,%2,%3}, {%4,%5,%6,%7}, {%8,%9}, {%0,%1,%2,%3};" \
    : "+f"((c)[0]), "+f"((c)[1]), "+f"((c)[2]), "+f"((c)[3]) \
    : "r"((A)[0]), "r"((A)[1]), "r"((A)[2]), "r"((A)[3]), "r"((B)[0]), "r"((B)[1]))

// pre-split all 5 weight matrices (f32 -> bf16 hi/lo), 8 elems/thread
__global__ void k_wsplit(const float* w0, const float* w1, const float* w2,
                         const float* w3, const float* w4) {
    int i = (blockIdx.x * blockDim.x + threadIdx.x) * 8;
    if (i >= 5 * 16384) return;
    int idx = i >> 14, off = i & 16383;
    const float* w = idx == 0 ? w0 : idx == 1 ? w1 : idx == 2 ? w2 : idx == 3 ? w3 : w4;
    uint32_t hw[4], lw[4];
#pragma unroll
    for (int q = 0; q < 4; q++) split2(w[off + 2 * q], w[off + 2 * q + 1], hw[q], lw[q]);
    *(uint4*)&g_wh[idx][off] = make_uint4(hw[0], hw[1], hw[2], hw[3]);
    *(uint4*)&g_wl[idx][off] = make_uint4(lw[0], lw[1], lw[2], lw[3]);
}

// stage pre-split agg rows (chunks 0-7 A operand): pure uint4 pass-through
__device__ __forceinline__ void ld_stage_agg(int row0, int kb, int tid, uint4& hw, uint4& lw) {
    int r = tid >> 1, h = tid & 1;
    int grow = row0 + r;
    if (grow < NN) {
        long long base = (long long)grow * FF + kb * 16 + h * 8;
        hw = *(const uint4*)&g_aggh[base];
        lw = *(const uint4*)&g_aggl[base];
    } else {
        hw = make_uint4(0, 0, 0, 0);
        lw = make_uint4(0, 0, 0, 0);
    }
}

__device__ __forceinline__ void ld_stage_a(const float* __restrict__ S, int row0,
                                           int kb, int tid, float v[8]) {
    int r = tid >> 1, h = tid & 1;
    int grow = row0 + r;
    if (grow < NN) {
        const float4* p = (const float4*)&S[(long long)grow * FF + kb * 16 + h * 8];
        float4 a = p[0], b = p[1];
        v[0] = a.x; v[1] = a.y; v[2] = a.z; v[3] = a.w;
        v[4] = b.x; v[5] = b.y; v[6] = b.z; v[7] = b.w;
    } else {
#pragma unroll
        for (int q = 0; q < 8; q++) v[q] = 0.f;
    }
}

__device__ __forceinline__ void st_stage_a(unsigned short* H, unsigned short* L,
                                           int tid, const float v[8]) {
    int r = tid >> 1, h = tid & 1;
    uint32_t hw[4], lw[4];
#pragma unroll
    for (int q = 0; q < 4; q++) split2(v[2 * q], v[2 * q + 1], hw[q], lw[q]);
    *(uint4*)&H[r * PADK + h * 8] = make_uint4(hw[0], hw[1], hw[2], hw[3]);
    *(uint4*)&L[r * PADK + h * 8] = make_uint4(lw[0], lw[1], lw[2], lw[3]);
}

__device__ __forceinline__ void ld_stage_w(int widx, int kb, int tid, uint4& hw, uint4& lw) {
    int r = tid >> 1, h = tid & 1;
    hw = *(const uint4*)&g_wh[widx][r * 128 + kb * 16 + h * 8];
    lw = *(const uint4*)&g_wl[widx][r * 128 + kb * 16 + h * 8];
}

__device__ __forceinline__ void st_stage_u(unsigned short* H, unsigned short* L,
                                           int tid, uint4 hw, uint4 lw) {
    int r = tid >> 1, h = tid & 1;
    *(uint4*)&H[r * PADK + h * 8] = hw;
    *(uint4*)&L[r * PADK + h * 8] = lw;
}

__global__ void __launch_bounds__(256, 1) k_mma(
    const float* __restrict__ A2,
    int wi1, int wi2,
    const float* __restrict__ bias, float* __restrict__ out1, int relu,
    int dec, const float* __restrict__ bdec, float* __restrict__ out2)
{
    extern __shared__ unsigned short smu[];
    unsigned short* AhS = smu;
    unsigned short* AlS = smu + 2 * CH;
    unsigned short* WhS = smu + 4 * CH;
    unsigned short* WlS = smu + 6 * CH;
    unsigned short* HhS = smu + 8 * CH;    // [8][CH], decoder only
    unsigned short* HlS = smu + 16 * CH;

    int tid = threadIdx.x, lane = tid & 31, wid = tid >> 5;
    int row0 = blockIdx.x * 128;
    int m_base = (wid & 1) * 64;
    int n_base = (wid >> 1) * 32;

    float acc[4][4][4];
#pragma unroll
    for (int mi = 0; mi < 4; mi++)
#pragma unroll
        for (int ni = 0; ni < 4; ni++)
#pragma unroll
            for (int q = 0; q < 4; q++) acc[mi][ni][q] = 0.f;

    int a_r = (lane & 7) + ((lane >> 3) & 1) * 8;
    int a_c = (lane >> 4) * 8;
    int b_r = lane & 7;
    int b_c = ((lane >> 3) & 1) * 8;

    float av[8];
    uint4 ahv, alv, whv, wlv;
    ld_stage_agg(row0, 0, tid, ahv, alv);
    ld_stage_w(wi1, 0, tid, whv, wlv);

    // chunks 0-7: A = pre-split agg; chunks 8-15: A = A2 rows (split on store)
    for (int c = 0; c < 16; c++) {
        int buf = c & 1;
        if (c < 8) st_stage_u(AhS + buf * CH, AlS + buf * CH, tid, ahv, alv);
        else       st_stage_a(AhS + buf * CH, AlS + buf * CH, tid, av);
        st_stage_u(WhS + buf * CH, WlS + buf * CH, tid, whv, wlv);
        __syncthreads();
        if (c + 1 < 16) {
            if (c + 1 < 8) ld_stage_agg(row0, c + 1, tid, ahv, alv);
            else           ld_stage_a(A2, row0, (c + 1) & 7, tid, av);
            ld_stage_w((c + 1 >= 8) ? wi2 : wi1, (c + 1) & 7, tid, whv, wlv);
        }
        uint32_t Ah4[4][4], Al4[4][4], Bh2[4][2], Bl2[4][2];
#pragma unroll
        for (int mi = 0; mi < 4; mi++) {
            LDSM_X4(Ah4[mi], smem_u32(&AhS[buf * CH + (m_base + mi * 16 + a_r) * PADK + a_c]));
            LDSM_X4(Al4[mi], smem_u32(&AlS[buf * CH + (m_base + mi * 16 + a_r) * PADK + a_c]));
        }
#pragma unroll
        for (int ni = 0; ni < 4; ni++) {
            LDSM_X2(Bh2[ni], smem_u32(&WhS[buf * CH + (n_base + ni * 8 + b_r) * PADK + b_c]));
            LDSM_X2(Bl2[ni], smem_u32(&WlS[buf * CH + (n_base + ni * 8 + b_r) * PADK + b_c]));
        }
#pragma unroll
        for (int mi = 0; mi < 4; mi++)
#pragma unroll
            for (int ni = 0; ni < 4; ni++) {
                MMA16816(acc[mi][ni], Ah4[mi], Bh2[ni]);
                MMA16816(acc[mi][ni], Ah4[mi], Bl2[ni]);
                MMA16816(acc[mi][ni], Al4[mi], Bh2[ni]);
            }
    }

    // epilogue: out1 = acc + bias (relu); if dec, also split h into Hhold smem
#pragma unroll
    for (int ni = 0; ni < 4; ni++) {
        int col = n_base + ni * 8 + (lane & 3) * 2;
        float b0 = bias[col], b1 = bias[col + 1];
        int chunk = col >> 4, kw = col & 15;
#pragma unroll
        for (int mi = 0; mi < 4; mi++) {
            int rr0 = m_base + mi * 16 + (lane >> 2);
            int rr1 = rr0 + 8;
            int r0 = row0 + rr0, r1 = row0 + rr1;
            float2 p0 = make_float2(acc[mi][ni][0] + b0, acc[mi][ni][1] + b1);
            float2 p1 = make_float2(acc[mi][ni][2] + b0, acc[mi][ni][3] + b1);
            if (relu) {
                p0.x = fmaxf(p0.x, 0.f); p0.y = fmaxf(p0.y, 0.f);
                p1.x = fmaxf(p1.x, 0.f); p1.y = fmaxf(p1.y, 0.f);
            }
            if (r0 < NN) *(float2*)&out1[(long long)r0 * FF + col] = p0;
            if (r1 < NN) *(float2*)&out1[(long long)r1 * FF + col] = p1;
            if (dec) {
                uint32_t hw, lw;
                split2(p0.x, p0.y, hw, lw);
                *(uint32_t*)&HhS[chunk * CH + rr0 * PADK + kw] = hw;
                *(uint32_t*)&HlS[chunk * CH + rr0 * PADK + kw] = lw;
                split2(p1.x, p1.y, hw, lw);
                *(uint32_t*)&HhS[chunk * CH + rr1 * PADK + kw] = hw;
                *(uint32_t*)&HlS[chunk * CH + rr1 * PADK + kw] = lw;
            }
        }
    }

    if (!dec) return;

    // decoder: dx = h @ wdec^T + bdec; A from Hhold, W ping-pong
#pragma unroll
    for (int mi = 0; mi < 4; mi++)
#pragma unroll
        for (int ni = 0; ni < 4; ni++)
#pragma unroll
            for (int q = 0; q < 4; q++) acc[mi][ni][q] = 0.f;

    ld_stage_w(4, 0, tid, whv, wlv);
    for (int c = 0; c < 8; c++) {
        int buf = c & 1;
        st_stage_u(WhS + buf * CH, WlS + buf * CH, tid, whv, wlv);
        __syncthreads();   // @c==0 also orders all epilogue Hhold writes before reads
        if (c + 1 < 8) ld_stage_w(4, c + 1, tid, whv, wlv);
        uint32_t Ah4[4][4], Al4[4][4], Bh2[4][2], Bl2[4][2];
#pragma unroll
        for (int mi = 0; mi < 4; mi++) {
            LDSM_X4(Ah4[mi], smem_u32(&HhS[c * CH + (m_base + mi * 16 + a_r) * PADK + a_c]));
            LDSM_X4(Al4[mi], smem_u32(&HlS[c * CH + (m_base + mi * 16 + a_r) * PADK + a_c]));
        }
#pragma unroll
        for (int ni = 0; ni < 4; ni++) {
            LDSM_X2(Bh2[ni], smem_u32(&WhS[buf * CH + (n_base + ni * 8 + b_r) * PADK + b_c]));
            LDSM_X2(Bl2[ni], smem_u32(&WlS[buf * CH + (n_base + ni * 8 + b_r) * PADK + b_c]));
        }
#pragma unroll
        for (int mi = 0; mi < 4; mi++)
#pragma unroll
            for (int ni = 0; ni < 4; ni++) {
                MMA16816(acc[mi][ni], Ah4[mi], Bh2[ni]);
                MMA16816(acc[mi][ni], Ah4[mi], Bl2[ni]);
                MMA16816(acc[mi][ni], Al4[mi], Bh2[ni]);
            }
    }

#pragma unroll
    for (int ni = 0; ni < 4; ni++) {
        int col = n_base + ni * 8 + (lane & 3) * 2;
        float b0 = bdec[col], b1 = bdec[col + 1];
#pragma unroll
        for (int mi = 0; mi < 4; mi++) {
            int r0 = row0 + m_base + mi * 16 + (lane >> 2);
            int r1 = r0 + 8;
            float2 p0 = make_float2(acc[mi][ni][0] + b0, acc[mi][ni][1] + b1);
            float2 p1 = make_float2(acc[mi][ni][2] + b0, acc[mi][ni][3] + b1);
            if (r0 < NN) *(float2*)&out2[(long long)r0 * FF + col] = p0;
            if (r1 < NN) *(float2*)&out2[(long long)r1 * FF + col] = p1;
        }
    }
}

// ---------------- launch ----------------
extern "C" void kernel_launch(void* const* d_in, const int* in_sizes, int n_in,
                              void* d_out, int out_size)
{
    const float* x    = (const float*)d_in[0];
    const void*  xe   = d_in[1];
    const float* w1l  = (const float*)d_in[2];
    const float* b1l  = (const float*)d_in[3];
    const float* w1r  = (const float*)d_in[4];
    const float* w2l  = (const float*)d_in[5];
    const float* b2l  = (const float*)d_in[6];
    const float* w2r  = (const float*)d_in[7];
    const float* wdec = (const float*)d_in[8];
    const float* bdec = (const float*)d_in[9];

    float* out_h  = (float*)d_out;
    float* out_dx = out_h + (long long)NN * FF;

    float* h1_p = nullptr;
    cudaGetSymbolAddress((void**)&h1_p, g_h1);

    cudaFuncSetAttribute(k_mma, cudaFuncAttributeMaxDynamicSharedMemorySize, SMEM_DEC_B);

    int nbScan = (NN + 511) / 512;
    int gE = (NE + 255) / 256;
    int gTc = (NN + 127) / 128;             // 782
    int gAgg = (NN + 7) / 8;

    k_init  <<<(NN + 255) / 256, 256>>>();
    k_wsplit<<<40, 256>>>(w1l, w1r, w2l, w2r, wdec);
    k_detect<<<gE, 256>>>((const int*)xe);
    k_deg   <<<gE, 256>>>(xe);
    k_scan1 <<<nbScan, 512>>>();
    k_scan2 <<<1, 512>>>(nbScan);
    k_scan3 <<<(NN + 511) / 512, 512>>>();
    k_fill  <<<gE, 256>>>(xe);

    // conv1
    k_agg<<<gAgg, 256>>>(x);
    k_mma<<<gTc, 256, SMEM_STAGE_B>>>(x, 0, 1, b1l, h1_p, 1, 0, nullptr, nullptr);
    // conv2 + decoder (fused)
    k_agg<<<gAgg, 256>>>(h1_p);
    k_mma<<<gTc, 256, SMEM_DEC_B>>>(h1_p, 2, 3, b2l, out_h, 0, 1, bdec, out_dx);
}

// round 16
// speedup vs baseline: 1.1492x; 1.0780x over previous
#include <cuda_runtime.h>
#include <cuda_bf16.h>
#include <cstdint>

#define NN 100000
#define NE 600000
#define FF 128

// ---------------- scratch (device globals; no allocation) ----------------
__device__ int   g_deg[NN];
__device__ int   g_off[NN];
__device__ int   g_cur[NN];
__device__ int   g_part[512];
__device__ int   g_csr[NE];
__device__ int   g_is64;
__device__ float g_agg[(long long)NN * FF];
__device__ float g_h1 [(long long)NN * FF];
__device__ unsigned short g_wh[5][128 * 128];   // pre-split weights: hi
__device__ unsigned short g_wl[5][128 * 128];   // pre-split weights: lo

// ---------------- init + edge dtype detection ----------------
__global__ void k_init() {
    int i = blockIdx.x * blockDim.x + threadIdx.x;
    if (i < NN) g_deg[i] = 0;
    if (i == 0) g_is64 = 1;
}

__global__ void k_detect(const int* __restrict__ xe) {
    int i = blockIdx.x * blockDim.x + threadIdx.x;
    if (i < NE) {
        if (xe[2 * i + 1] != 0) g_is64 = 0;
    }
}

__device__ __forceinline__ int eidx(const void* xe, int is64, long long i) {
    if (is64) return (int)((const long long*)xe)[i];
    return ((const int*)xe)[i];
}

// ---------------- CSR build ----------------
__global__ void k_deg(const void* __restrict__ xe) {
    int e = blockIdx.x * blockDim.x + threadIdx.x;
    if (e >= NE) return;
    int is64 = g_is64;
    int d = eidx(xe, is64, (long long)NE + e);
    atomicAdd(&g_deg[d], 1);
}

__global__ void k_scan1() {
    __shared__ int sh[512];
    int tid = threadIdx.x;
    int i = blockIdx.x * 512 + tid;
    int v = (i < NN) ? g_deg[i] : 0;
    sh[tid] = v;
    __syncthreads();
    for (int off = 1; off < 512; off <<= 1) {
        int t = 0;
        if (tid >= off) t = sh[tid - off];
        __syncthreads();
        sh[tid] += t;
        __syncthreads();
    }
    if (i < NN) g_off[i] = sh[tid] - v;
    if (tid == 511) g_part[blockIdx.x] = sh[511];
}

__global__ void k_scan2(int nb) {
    __shared__ int sh[512];
    int tid = threadIdx.x;
    int v = (tid < nb) ? g_part[tid] : 0;
    sh[tid] = v;
    __syncthreads();
    for (int off = 1; off < 512; off <<= 1) {
        int t = 0;
        if (tid >= off) t = sh[tid - off];
        __syncthreads();
        sh[tid] += t;
        __syncthreads();
    }
    if (tid < nb) g_part[tid] = sh[tid] - v;
}

__global__ void k_scan3() {
    int i = blockIdx.x * blockDim.x + threadIdx.x;
    if (i < NN) {
        int o = g_off[i] + g_part[i >> 9];
        g_off[i] = o;
        g_cur[i] = o;
    }
}

__global__ void k_fill(const void* __restrict__ xe) {
    int e = blockIdx.x * blockDim.x + threadIdx.x;
    if (e >= NE) return;
    int is64 = g_is64;
    int s = eidx(xe, is64, e);
    int d = eidx(xe, is64, (long long)NE + e);
    int p = atomicAdd(&g_cur[d], 1);
    g_csr[p] = s;
}

// ---------------- mean aggregation: one warp per node, float4 lanes, MLP=4 ----------------
__global__ void k_agg(const float* __restrict__ X, float* __restrict__ out) {
    int wid  = (blockIdx.x * blockDim.x + threadIdx.x) >> 5;
    int lane = threadIdx.x & 31;
    if (wid >= NN) return;
    int beg = g_off[wid];
    int d   = g_deg[wid];
    float4 s = make_float4(0.f, 0.f, 0.f, 0.f);
    int i = 0;
    for (; i + 4 <= d; i += 4) {
        int s0 = g_csr[beg + i];
        int s1 = g_csr[beg + i + 1];
        int s2 = g_csr[beg + i + 2];
        int s3 = g_csr[beg + i + 3];
        float4 v0 = *(const float4*)&X[(long long)s0 * FF + lane * 4];
        float4 v1 = *(const float4*)&X[(long long)s1 * FF + lane * 4];
        float4 v2 = *(const float4*)&X[(long long)s2 * FF + lane * 4];
        float4 v3 = *(const float4*)&X[(long long)s3 * FF + lane * 4];
        s.x += (v0.x + v1.x) + (v2.x + v3.x);
        s.y += (v0.y + v1.y) + (v2.y + v3.y);
        s.z += (v0.z + v1.z) + (v2.z + v3.z);
        s.w += (v0.w + v1.w) + (v2.w + v3.w);
    }
    for (; i < d; i++) {
        int s0 = g_csr[beg + i];
        float4 v0 = *(const float4*)&X[(long long)s0 * FF + lane * 4];
        s.x += v0.x; s.y += v0.y; s.z += v0.z; s.w += v0.w;
    }
    float inv = 1.0f / (float)(d > 0 ? d : 1);
    float4 r = make_float4(s.x * inv, s.y * inv, s.z * inv, s.w * inv);
    *(float4*)&out[(long long)wid * FF + lane * 4] = r;
}

// ================= bf16 split GEMM via mma.sync =================
#define PADK 24
#define CH (128 * PADK)                 // ushorts per chunk-tile
// dynamic smem layout (ushort units):
//   Ah[2][CH]@0  Al@6144  Wh@12288  Wl@18432  Hh[8][CH]@24576  Hl@49152
#define SMEM_STAGE_B (24576 * 2)        // conv-only: 48 KB
#define SMEM_DEC_B   (73728 * 2)        // conv2+decoder: 144 KB

__device__ __forceinline__ uint32_t smem_u32(const void* p) {
    uint32_t a;
    asm("{ .reg .u64 t; cvta.to.shared.u64 t, %1; cvt.u32.u64 %0, t; }" : "=r"(a) : "l"(p));
    return a;
}

#define LDSM_X4(r, a) asm volatile( \
    "ldmatrix.sync.aligned.m8n8.x4.shared.b16 {%0,%1,%2,%3}, [%4];" \
    : "=r"((r)[0]), "=r"((r)[1]), "=r"((r)[2]), "=r"((r)[3]) : "r"(a))
#define LDSM_X2(r, a) asm volatile( \
    "ldmatrix.sync.aligned.m8n8.x2.shared.b16 {%0,%1}, [%2];" \
    : "=r"((r)[0]), "=r"((r)[1]) : "r"(a))
#define MMA16816(c, A, B) asm volatile( \
    "mma.sync.aligned.m16n8k16.row.col.f32.bf16.bf16.f32 " \
    "{%0,%1,%2,%3}, {%4,%5,%6,%7}, {%8,%9}, {%0,%1,%2,%3};" \
    : "+f"((c)[0]), "+f"((c)[1]), "+f"((c)[2]), "+f"((c)[3]) \
    : "r"((A)[0]), "r"((A)[1]), "r"((A)[2]), "r"((A)[3]), "r"((B)[0]), "r"((B)[1]))

__device__ __forceinline__ void split2(float f0, float f1, uint32_t& hw, uint32_t& lw) {
    asm("cvt.rn.bf16x2.f32 %0, %1, %2;" : "=r"(hw) : "f"(f1), "f"(f0));
    float h0 = __uint_as_float(hw << 16);
    float h1 = __uint_as_float(hw & 0xffff0000u);
    float r0 = f0 - h0, r1 = f1 - h1;
    asm("cvt.rn.bf16x2.f32 %0, %1, %2;" : "=r"(lw) : "f"(r1), "f"(r0));
}

// pre-split all 5 weight matrices (f32 -> bf16 hi/lo), 8 elems/thread
__global__ void k_wsplit(const float* w0, const float* w1, const float* w2,
                         const float* w3, const float* w4) {
    int i = (blockIdx.x * blockDim.x + threadIdx.x) * 8;
    if (i >= 5 * 16384) return;
    int idx = i >> 14, off = i & 16383;
    const float* w = idx == 0 ? w0 : idx == 1 ? w1 : idx == 2 ? w2 : idx == 3 ? w3 : w4;
    uint32_t hw[4], lw[4];
#pragma unroll
    for (int q = 0; q < 4; q++) split2(w[off + 2 * q], w[off + 2 * q + 1], hw[q], lw[q]);
    *(uint4*)&g_wh[idx][off] = make_uint4(hw[0], hw[1], hw[2], hw[3]);
    *(uint4*)&g_wl[idx][off] = make_uint4(lw[0], lw[1], lw[2], lw[3]);
}

__device__ __forceinline__ void ld_stage_a(const float* __restrict__ S, int row0,
                                           int kb, int tid, float v[8]) {
    int r = tid >> 1, h = tid & 1;
    int grow = row0 + r;
    if (grow < NN) {
        const float4* p = (const float4*)&S[(long long)grow * FF + kb * 16 + h * 8];
        float4 a = p[0], b = p[1];
        v[0] = a.x; v[1] = a.y; v[2] = a.z; v[3] = a.w;
        v[4] = b.x; v[5] = b.y; v[6] = b.z; v[7] = b.w;
    } else {
#pragma unroll
        for (int q = 0; q < 8; q++) v[q] = 0.f;
    }
}

__device__ __forceinline__ void st_stage_a(unsigned short* H, unsigned short* L,
                                           int tid, const float v[8]) {
    int r = tid >> 1, h = tid & 1;
    uint32_t hw[4], lw[4];
#pragma unroll
    for (int q = 0; q < 4; q++) split2(v[2 * q], v[2 * q + 1], hw[q], lw[q]);
    *(uint4*)&H[r * PADK + h * 8] = make_uint4(hw[0], hw[1], hw[2], hw[3]);
    *(uint4*)&L[r * PADK + h * 8] = make_uint4(lw[0], lw[1], lw[2], lw[3]);
}

__device__ __forceinline__ void ld_stage_w(int widx, int kb, int tid, uint4& hw, uint4& lw) {
    int r = tid >> 1, h = tid & 1;
    hw = *(const uint4*)&g_wh[widx][r * 128 + kb * 16 + h * 8];
    lw = *(const uint4*)&g_wl[widx][r * 128 + kb * 16 + h * 8];
}

__device__ __forceinline__ void st_stage_u(unsigned short* H, unsigned short* L,
                                           int tid, uint4 hw, uint4 lw) {
    int r = tid >> 1, h = tid & 1;
    *(uint4*)&H[r * PADK + h * 8] = hw;
    *(uint4*)&L[r * PADK + h * 8] = lw;
}

// ---------------- conv-only GEMM: 48 KB smem, 2 CTAs/SM ----------------
__global__ void __launch_bounds__(256, 2) k_mma_c(
    const float* __restrict__ A1, const float* __restrict__ A2,
    int wi1, int wi2,
    const float* __restrict__ bias, float* __restrict__ out1, int relu)
{
    extern __shared__ unsigned short smu[];
    unsigned short* AhS = smu;
    unsigned short* AlS = smu + 2 * CH;
    unsigned short* WhS = smu + 4 * CH;
    unsigned short* WlS = smu + 6 * CH;

    int tid = threadIdx.x, lane = tid & 31, wid = tid >> 5;
    int row0 = blockIdx.x * 128;
    int m_base = (wid & 1) * 64;
    int n_base = (wid >> 1) * 32;

    float acc[4][4][4];
#pragma unroll
    for (int mi = 0; mi < 4; mi++)
#pragma unroll
        for (int ni = 0; ni < 4; ni++)
#pragma unroll
            for (int q = 0; q < 4; q++) acc[mi][ni][q] = 0.f;

    int a_r = (lane & 7) + ((lane >> 3) & 1) * 8;
    int a_c = (lane >> 4) * 8;
    int b_r = lane & 7;
    int b_c = ((lane >> 3) & 1) * 8;

    float av[8];
    uint4 whv, wlv;
    ld_stage_a(A1, row0, 0, tid, av);
    ld_stage_w(wi1, 0, tid, whv, wlv);

    for (int c = 0; c < 16; c++) {
        int buf = c & 1;
        st_stage_a(AhS + buf * CH, AlS + buf * CH, tid, av);
        st_stage_u(WhS + buf * CH, WlS + buf * CH, tid, whv, wlv);
        __syncthreads();
        if (c + 1 < 16) {
            ld_stage_a((c + 1 >= 8) ? A2 : A1, row0, (c + 1) & 7, tid, av);
            ld_stage_w((c + 1 >= 8) ? wi2 : wi1, (c + 1) & 7, tid, whv, wlv);
        }
        uint32_t Ah4[4][4], Al4[4][4], Bh2[4][2], Bl2[4][2];
#pragma unroll
        for (int mi = 0; mi < 4; mi++) {
            LDSM_X4(Ah4[mi], smem_u32(&AhS[buf * CH + (m_base + mi * 16 + a_r) * PADK + a_c]));
            LDSM_X4(Al4[mi], smem_u32(&AlS[buf * CH + (m_base + mi * 16 + a_r) * PADK + a_c]));
        }
#pragma unroll
        for (int ni = 0; ni < 4; ni++) {
            LDSM_X2(Bh2[ni], smem_u32(&WhS[buf * CH + (n_base + ni * 8 + b_r) * PADK + b_c]));
            LDSM_X2(Bl2[ni], smem_u32(&WlS[buf * CH + (n_base + ni * 8 + b_r) * PADK + b_c]));
        }
#pragma unroll
        for (int mi = 0; mi < 4; mi++)
#pragma unroll
            for (int ni = 0; ni < 4; ni++) {
                MMA16816(acc[mi][ni], Ah4[mi], Bh2[ni]);
                MMA16816(acc[mi][ni], Ah4[mi], Bl2[ni]);
                MMA16816(acc[mi][ni], Al4[mi], Bh2[ni]);
            }
    }

#pragma unroll
    for (int ni = 0; ni < 4; ni++) {
        int col = n_base + ni * 8 + (lane & 3) * 2;
        float b0 = bias[col], b1 = bias[col + 1];
#pragma unroll
        for (int mi = 0; mi < 4; mi++) {
            int r0 = row0 + m_base + mi * 16 + (lane >> 2);
            int r1 = r0 + 8;
            float2 p0 = make_float2(acc[mi][ni][0] + b0, acc[mi][ni][1] + b1);
            float2 p1 = make_float2(acc[mi][ni][2] + b0, acc[mi][ni][3] + b1);
            if (relu) {
                p0.x = fmaxf(p0.x, 0.f); p0.y = fmaxf(p0.y, 0.f);
                p1.x = fmaxf(p1.x, 0.f); p1.y = fmaxf(p1.y, 0.f);
            }
            if (r0 < NN) *(float2*)&out1[(long long)r0 * FF + col] = p0;
            if (r1 < NN) *(float2*)&out1[(long long)r1 * FF + col] = p1;
        }
    }
}

// ---------------- conv + decoder GEMM: 144 KB smem, 1 CTA/SM ----------------
__global__ void __launch_bounds__(256, 1) k_mma_d(
    const float* __restrict__ A1, const float* __restrict__ A2,
    int wi1, int wi2,
    const float* __restrict__ bias, float* __restrict__ out1,
    const float* __restrict__ bdec, float* __restrict__ out2)
{
    extern __shared__ unsigned short smu[];
    unsigned short* AhS = smu;
    unsigned short* AlS = smu + 2 * CH;
    unsigned short* WhS = smu + 4 * CH;
    unsigned short* WlS = smu + 6 * CH;
    unsigned short* HhS = smu + 8 * CH;    // [8][CH]
    unsigned short* HlS = smu + 16 * CH;

    int tid = threadIdx.x, lane = tid & 31, wid = tid >> 5;
    int row0 = blockIdx.x * 128;
    int m_base = (wid & 1) * 64;
    int n_base = (wid >> 1) * 32;

    float acc[4][4][4];
#pragma unroll
    for (int mi = 0; mi < 4; mi++)
#pragma unroll
        for (int ni = 0; ni < 4; ni++)
#pragma unroll
            for (int q = 0; q < 4; q++) acc[mi][ni][q] = 0.f;

    int a_r = (lane & 7) + ((lane >> 3) & 1) * 8;
    int a_c = (lane >> 4) * 8;
    int b_r = lane & 7;
    int b_c = ((lane >> 3) & 1) * 8;

    float av[8];
    uint4 whv, wlv;
    ld_stage_a(A1, row0, 0, tid, av);
    ld_stage_w(wi1, 0, tid, whv, wlv);

    for (int c = 0; c < 16; c++) {
        int buf = c & 1;
        st_stage_a(AhS + buf * CH, AlS + buf * CH, tid, av);
        st_stage_u(WhS + buf * CH, WlS + buf * CH, tid, whv, wlv);
        __syncthreads();
        if (c + 1 < 16) {
            ld_stage_a((c + 1 >= 8) ? A2 : A1, row0, (c + 1) & 7, tid, av);
            ld_stage_w((c + 1 >= 8) ? wi2 : wi1, (c + 1) & 7, tid, whv, wlv);
        }
        uint32_t Ah4[4][4], Al4[4][4], Bh2[4][2], Bl2[4][2];
#pragma unroll
        for (int mi = 0; mi < 4; mi++) {
            LDSM_X4(Ah4[mi], smem_u32(&AhS[buf * CH + (m_base + mi * 16 + a_r) * PADK + a_c]));
            LDSM_X4(Al4[mi], smem_u32(&AlS[buf * CH + (m_base + mi * 16 + a_r) * PADK + a_c]));
        }
#pragma unroll
        for (int ni = 0; ni < 4; ni++) {
            LDSM_X2(Bh2[ni], smem_u32(&WhS[buf * CH + (n_base + ni * 8 + b_r) * PADK + b_c]));
            LDSM_X2(Bl2[ni], smem_u32(&WlS[buf * CH + (n_base + ni * 8 + b_r) * PADK + b_c]));
        }
#pragma unroll
        for (int mi = 0; mi < 4; mi++)
#pragma unroll
            for (int ni = 0; ni < 4; ni++) {
                MMA16816(acc[mi][ni], Ah4[mi], Bh2[ni]);
                MMA16816(acc[mi][ni], Ah4[mi], Bl2[ni]);
                MMA16816(acc[mi][ni], Al4[mi], Bh2[ni]);
            }
    }

    // epilogue: out1 = acc + bias; split h into Hhold smem
#pragma unroll
    for (int ni = 0; ni < 4; ni++) {
        int col = n_base + ni * 8 + (lane & 3) * 2;
        float b0 = bias[col], b1 = bias[col + 1];
        int chunk = col >> 4, kw = col & 15;
#pragma unroll
        for (int mi = 0; mi < 4; mi++) {
            int rr0 = m_base + mi * 16 + (lane >> 2);
            int rr1 = rr0 + 8;
            int r0 = row0 + rr0, r1 = row0 + rr1;
            float2 p0 = make_float2(acc[mi][ni][0] + b0, acc[mi][ni][1] + b1);
            float2 p1 = make_float2(acc[mi][ni][2] + b0, acc[mi][ni][3] + b1);
            if (r0 < NN) *(float2*)&out1[(long long)r0 * FF + col] = p0;
            if (r1 < NN) *(float2*)&out1[(long long)r1 * FF + col] = p1;
            uint32_t hw, lw;
            split2(p0.x, p0.y, hw, lw);
            *(uint32_t*)&HhS[chunk * CH + rr0 * PADK + kw] = hw;
            *(uint32_t*)&HlS[chunk * CH + rr0 * PADK + kw] = lw;
            split2(p1.x, p1.y, hw, lw);
            *(uint32_t*)&HhS[chunk * CH + rr1 * PADK + kw] = hw;
            *(uint32_t*)&HlS[chunk * CH + rr1 * PADK + kw] = lw;
        }
    }

    // decoder: dx = h @ wdec^T + bdec; A from Hhold, W ping-pong
#pragma unroll
    for (int mi = 0; mi < 4; mi++)
#pragma unroll
        for (int ni = 0; ni < 4; ni++)
#pragma unroll
            for (int q = 0; q < 4; q++) acc[mi][ni][q] = 0.f;

    ld_stage_w(4, 0, tid, whv, wlv);
    for (int c = 0; c < 8; c++) {
        int buf = c & 1;
        st_stage_u(WhS + buf * CH, WlS + buf * CH, tid, whv, wlv);
        __syncthreads();   // @c==0 also orders all epilogue Hhold writes before reads
        if (c + 1 < 8) ld_stage_w(4, c + 1, tid, whv, wlv);
        uint32_t Ah4[4][4], Al4[4][4], Bh2[4][2], Bl2[4][2];
#pragma unroll
        for (int mi = 0; mi < 4; mi++) {
            LDSM_X4(Ah4[mi], smem_u32(&HhS[c * CH + (m_base + mi * 16 + a_r) * PADK + a_c]));
            LDSM_X4(Al4[mi], smem_u32(&HlS[c * CH + (m_base + mi * 16 + a_r) * PADK + a_c]));
        }
#pragma unroll
        for (int ni = 0; ni < 4; ni++) {
            LDSM_X2(Bh2[ni], smem_u32(&WhS[buf * CH + (n_base + ni * 8 + b_r) * PADK + b_c]));
            LDSM_X2(Bl2[ni], smem_u32(&WlS[buf * CH + (n_base + ni * 8 + b_r) * PADK + b_c]));
        }
#pragma unroll
        for (int mi = 0; mi < 4; mi++)
#pragma unroll
            for (int ni = 0; ni < 4; ni++) {
                MMA16816(acc[mi][ni], Ah4[mi], Bh2[ni]);
                MMA16816(acc[mi][ni], Ah4[mi], Bl2[ni]);
                MMA16816(acc[mi][ni], Al4[mi], Bh2[ni]);
            }
    }

#pragma unroll
    for (int ni = 0; ni < 4; ni++) {
        int col = n_base + ni * 8 + (lane & 3) * 2;
        float b0 = bdec[col], b1 = bdec[col + 1];
#pragma unroll
        for (int mi = 0; mi < 4; mi++) {
            int r0 = row0 + m_base + mi * 16 + (lane >> 2);
            int r1 = r0 + 8;
            float2 p0 = make_float2(acc[mi][ni][0] + b0, acc[mi][ni][1] + b1);
            float2 p1 = make_float2(acc[mi][ni][2] + b0, acc[mi][ni][3] + b1);
            if (r0 < NN) *(float2*)&out2[(long long)r0 * FF + col] = p0;
            if (r1 < NN) *(float2*)&out2[(long long)r1 * FF + col] = p1;
        }
    }
}

// ---------------- launch ----------------
extern "C" void kernel_launch(void* const* d_in, const int* in_sizes, int n_in,
                              void* d_out, int out_size)
{
    const float* x    = (const float*)d_in[0];
    const void*  xe   = d_in[1];
    const float* w1l  = (const float*)d_in[2];
    const float* b1l  = (const float*)d_in[3];
    const float* w1r  = (const float*)d_in[4];
    const float* w2l  = (const float*)d_in[5];
    const float* b2l  = (const float*)d_in[6];
    const float* w2r  = (const float*)d_in[7];
    const float* wdec = (const float*)d_in[8];
    const float* bdec = (const float*)d_in[9];

    float* out_h  = (float*)d_out;
    float* out_dx = out_h + (long long)NN * FF;

    float *agg_p = nullptr, *h1_p = nullptr;
    cudaGetSymbolAddress((void**)&agg_p, g_agg);
    cudaGetSymbolAddress((void**)&h1_p,  g_h1);

    cudaFuncSetAttribute(k_mma_c, cudaFuncAttributeMaxDynamicSharedMemorySize, SMEM_STAGE_B);
    cudaFuncSetAttribute(k_mma_d, cudaFuncAttributeMaxDynamicSharedMemorySize, SMEM_DEC_B);

    int nbScan = (NN + 511) / 512;
    int gE = (NE + 255) / 256;
    int gTc = (NN + 127) / 128;             // 782
    int gAgg = (NN + 7) / 8;

    k_init  <<<(NN + 255) / 256, 256>>>();
    k_wsplit<<<40, 256>>>(w1l, w1r, w2l, w2r, wdec);
    k_detect<<<gE, 256>>>((const int*)xe);
    k_deg   <<<gE, 256>>>(xe);
    k_scan1 <<<nbScan, 512>>>();
    k_scan2 <<<1, 512>>>(nbScan);
    k_scan3 <<<(NN + 511) / 512, 512>>>();
    k_fill  <<<gE, 256>>>(xe);

    // conv1 (2 CTAs/SM GEMM)
    k_agg  <<<gAgg, 256>>>(x, agg_p);
    k_mma_c<<<gTc, 256, SMEM_STAGE_B>>>(agg_p, x, 0, 1, b1l, h1_p, 1);
    // conv2 + decoder (fused, 1 CTA/SM)
    k_agg  <<<gAgg, 256>>>(h1_p, agg_p);
    k_mma_d<<<gTc, 256, SMEM_DEC_B>>>(agg_p, h1_p, 2, 3, b2l, out_h, bdec, out_dx);
}